// round 2
// baseline (speedup 1.0000x reference)
#include <cuda_runtime.h>
#include <math.h>
#include <stdint.h>

#define N_NODES 100000
#define N_EDGES 800000

typedef unsigned long long u64t;

// ---------------- scratch (static __device__ — no allocations allowed) ----------
__device__ float g_AB[(size_t)N_NODES * 256];    // [n][0:128]=x@W1a, [n][128:256]=x@W1b
__device__ float g_Hagg[(size_t)N_NODES * 128];  // sum over in-edges of relu(h)
__device__ float g_G[(size_t)N_NODES * 128];     // relu(update hidden)
__device__ float g_deg[N_NODES];                 // in-degree (float)
__device__ float g_Wcat[192 * 128];              // [U1a (64x128) ; V = W2@U1b (128x128)]
__device__ float g_dvec[128];                    // b2 @ U1b

// packed f32x2 fma (FFMA2) — only reachable via PTX
__device__ __forceinline__ u64t fma2(u64t a, u64t b, u64t c) {
    u64t d;
    asm("fma.rn.f32x2 %0, %1, %2, %3;" : "=l"(d) : "l"(a), "l"(b), "l"(c));
    return d;
}

union F4U2 { float4 f; u64t u[2]; };

// ---------------- prep: build Wcat and dvec --------------------------------------
__global__ void prep_kernel(const float* __restrict__ W2, const float* __restrict__ b2,
                            const float* __restrict__ U1) {
    int b = blockIdx.x, j = threadIdx.x;  // 128 threads
    if (b < 64) {
        g_Wcat[b * 128 + j] = U1[b * 128 + j];                 // U1a row b
    } else if (b < 192) {
        int i = b - 64;                                        // V row i
        float s = 0.f;
#pragma unroll
        for (int k = 0; k < 64; k++)
            s = fmaf(W2[i * 64 + k], U1[(64 + k) * 128 + j], s);
        g_Wcat[b * 128 + j] = s;
    } else {
        float s = 0.f;
#pragma unroll
        for (int k = 0; k < 64; k++)
            s = fmaf(b2[k], U1[(64 + k) * 128 + j], s);
        g_dvec[j] = s;
    }
}

// ---------------- zero scratch accumulators ---------------------------------------
__global__ void zero_kernel() {
    size_t idx = (size_t)blockIdx.x * blockDim.x + threadIdx.x;
    size_t stride = (size_t)gridDim.x * blockDim.x;
    size_t tot4 = (size_t)N_NODES * 128 / 4;
    float4 z = make_float4(0.f, 0.f, 0.f, 0.f);
    for (size_t i = idx; i < tot4; i += stride) ((float4*)g_Hagg)[i] = z;
    for (size_t i = idx; i < (size_t)N_NODES; i += stride) g_deg[i] = 0.f;
}

// ---------------- GEMM1: AB = x @ [W1a | W1b]   (M=100000, K=64, N=2x128) ---------
__global__ __launch_bounds__(256) void gemm_ab_kernel(const float* __restrict__ x,
                                                      const float* __restrict__ W1) {
    __shared__ float2 As[32][65];   // duplicated A: (v, v) per element
    __shared__ float  Bs[32][128];
    int row0 = blockIdx.x * 64;
    int cb = blockIdx.y;
    const float* Wb = W1 + (size_t)cb * 64 * 128;
    int tid = threadIdx.x;
    int r0 = (tid >> 4) * 4;
    int c0 = (tid & 15) * 8;
    u64t acc2[4][4];
#pragma unroll
    for (int i = 0; i < 4; i++)
#pragma unroll
        for (int j = 0; j < 4; j++) acc2[i][j] = 0ull;

    for (int k0 = 0; k0 < 64; k0 += 32) {
#pragma unroll
        for (int it = 0; it < 8; it++) {
            int t = tid + it * 256;
            int k = t & 31, m = t >> 5;
            int gm = row0 + m;
            float v = (gm < N_NODES) ? x[(size_t)gm * 64 + k0 + k] : 0.f;
            As[k][m] = make_float2(v, v);
        }
#pragma unroll
        for (int it = 0; it < 4; it++) {
            int t = tid + it * 256;
            int k = t >> 5, j4 = t & 31;
            *(float4*)&Bs[k][j4 * 4] = *(const float4*)(Wb + (size_t)(k0 + k) * 128 + j4 * 4);
        }
        __syncthreads();
#pragma unroll
        for (int k = 0; k < 32; k++) {
            u64t a0 = *(const u64t*)&As[k][r0 + 0];
            u64t a1 = *(const u64t*)&As[k][r0 + 1];
            u64t a2 = *(const u64t*)&As[k][r0 + 2];
            u64t a3 = *(const u64t*)&As[k][r0 + 3];
            F4U2 B0, B1;
            B0.f = *(float4*)&Bs[k][c0];
            B1.f = *(float4*)&Bs[k][c0 + 4];
#pragma unroll
            for (int p = 0; p < 2; p++) {
                acc2[0][p]     = fma2(a0, B0.u[p], acc2[0][p]);
                acc2[1][p]     = fma2(a1, B0.u[p], acc2[1][p]);
                acc2[2][p]     = fma2(a2, B0.u[p], acc2[2][p]);
                acc2[3][p]     = fma2(a3, B0.u[p], acc2[3][p]);
                acc2[0][2 + p] = fma2(a0, B1.u[p], acc2[0][2 + p]);
                acc2[1][2 + p] = fma2(a1, B1.u[p], acc2[1][2 + p]);
                acc2[2][2 + p] = fma2(a2, B1.u[p], acc2[2][2 + p]);
                acc2[3][2 + p] = fma2(a3, B1.u[p], acc2[3][2 + p]);
            }
        }
        __syncthreads();
    }
#pragma unroll
    for (int i = 0; i < 4; i++) {
        int gm = row0 + r0 + i;
        if (gm < N_NODES) {
            float* o = g_AB + (size_t)gm * 256 + cb * 128 + c0;
            F4U2 O0, O1;
            O0.u[0] = acc2[i][0]; O0.u[1] = acc2[i][1];
            O1.u[0] = acc2[i][2]; O1.u[1] = acc2[i][3];
            *(float4*)o = O0.f;
            *(float4*)(o + 4) = O1.f;
        }
    }
}

// ---------------- edge kernel: h=relu(A[src]+B[dst]+log1p(ef)@W1c+b1), RED into Hagg
// 2 edges per warp for higher memory-level parallelism.
__global__ __launch_bounds__(256) void edge_kernel(const int* __restrict__ ei,
                                                   const float* __restrict__ ef,
                                                   const float* __restrict__ W1,
                                                   const float* __restrict__ b1) {
    __shared__ float s_wc[512];   // W1 rows 128..131 (edge-feature rows)
    __shared__ float s_b1[128];
    for (int t = threadIdx.x; t < 512; t += 256) s_wc[t] = W1[128 * 128 + t];
    if (threadIdx.x < 128) s_b1[threadIdx.x] = b1[threadIdx.x];
    __syncthreads();

    int warp = threadIdx.x >> 5;
    int lane = threadIdx.x & 31;
    int e0 = (blockIdx.x * 8 + warp) * 2;   // grid sized exactly: 800000/16

    int s0 = ei[e0],            s1 = ei[e0 + 1];
    int d0 = ei[N_EDGES + e0],  d1 = ei[N_EDGES + e0 + 1];

    // issue all four 512B gathers up front
    float4 a0 = *(const float4*)(g_AB + (size_t)s0 * 256 + lane * 4);
    float4 a1 = *(const float4*)(g_AB + (size_t)s1 * 256 + lane * 4);
    float4 b0 = *(const float4*)(g_AB + (size_t)d0 * 256 + 128 + lane * 4);
    float4 b1v = *(const float4*)(g_AB + (size_t)d1 * 256 + 128 + lane * 4);

    float mv = 0.f;
    if (lane < 8) mv = log1pf(ef[(size_t)e0 * 4 + lane]);  // 8 contiguous feats = both edges

    float4 w0 = *(const float4*)&s_wc[0 * 128 + lane * 4];
    float4 w1 = *(const float4*)&s_wc[1 * 128 + lane * 4];
    float4 w2 = *(const float4*)&s_wc[2 * 128 + lane * 4];
    float4 w3 = *(const float4*)&s_wc[3 * 128 + lane * 4];
    float4 bb = *(const float4*)&s_b1[lane * 4];

    {
        float l0 = __shfl_sync(0xffffffffu, mv, 0);
        float l1 = __shfl_sync(0xffffffffu, mv, 1);
        float l2 = __shfl_sync(0xffffffffu, mv, 2);
        float l3 = __shfl_sync(0xffffffffu, mv, 3);
        float4 h;
        h.x = fmaxf(fmaf(l3, w3.x, fmaf(l2, w2.x, fmaf(l1, w1.x, fmaf(l0, w0.x, a0.x + b0.x + bb.x)))), 0.f);
        h.y = fmaxf(fmaf(l3, w3.y, fmaf(l2, w2.y, fmaf(l1, w1.y, fmaf(l0, w0.y, a0.y + b0.y + bb.y)))), 0.f);
        h.z = fmaxf(fmaf(l3, w3.z, fmaf(l2, w2.z, fmaf(l1, w1.z, fmaf(l0, w0.z, a0.z + b0.z + bb.z)))), 0.f);
        h.w = fmaxf(fmaf(l3, w3.w, fmaf(l2, w2.w, fmaf(l1, w1.w, fmaf(l0, w0.w, a0.w + b0.w + bb.w)))), 0.f);
        atomicAdd((float4*)(g_Hagg + (size_t)d0 * 128 + lane * 4), h);
    }
    {
        float l0 = __shfl_sync(0xffffffffu, mv, 4);
        float l1 = __shfl_sync(0xffffffffu, mv, 5);
        float l2 = __shfl_sync(0xffffffffu, mv, 6);
        float l3 = __shfl_sync(0xffffffffu, mv, 7);
        float4 h;
        h.x = fmaxf(fmaf(l3, w3.x, fmaf(l2, w2.x, fmaf(l1, w1.x, fmaf(l0, w0.x, a1.x + b1v.x + bb.x)))), 0.f);
        h.y = fmaxf(fmaf(l3, w3.y, fmaf(l2, w2.y, fmaf(l1, w1.y, fmaf(l0, w0.y, a1.y + b1v.y + bb.y)))), 0.f);
        h.z = fmaxf(fmaf(l3, w3.z, fmaf(l2, w2.z, fmaf(l1, w1.z, fmaf(l0, w0.z, a1.z + b1v.z + bb.z)))), 0.f);
        h.w = fmaxf(fmaf(l3, w3.w, fmaf(l2, w2.w, fmaf(l1, w1.w, fmaf(l0, w0.w, a1.w + b1v.w + bb.w)))), 0.f);
        atomicAdd((float4*)(g_Hagg + (size_t)d1 * 128 + lane * 4), h);
    }
    if (lane == 0) atomicAdd(&g_deg[d0], 1.0f);
    if (lane == 1) atomicAdd(&g_deg[d1], 1.0f);
}

// ---------------- GEMM2: G = relu([x|Hagg] @ Wcat + deg*dvec + bu1)  (K=192, N=128)
__global__ __launch_bounds__(256) void gemm_upd1_kernel(const float* __restrict__ x,
                                                        const float* __restrict__ bu1) {
    __shared__ float2 As[32][65];
    __shared__ float  Bs[32][128];
    int row0 = blockIdx.x * 64;
    int tid = threadIdx.x;
    int r0 = (tid >> 4) * 4;
    int c0 = (tid & 15) * 8;
    u64t acc2[4][4];
#pragma unroll
    for (int i = 0; i < 4; i++)
#pragma unroll
        for (int j = 0; j < 4; j++) acc2[i][j] = 0ull;

    for (int k0 = 0; k0 < 192; k0 += 32) {
        bool isx = (k0 < 64);
#pragma unroll
        for (int it = 0; it < 8; it++) {
            int t = tid + it * 256;
            int k = t & 31, m = t >> 5;
            int gm = row0 + m;
            float v = 0.f;
            if (gm < N_NODES) {
                int gk = k0 + k;
                v = isx ? x[(size_t)gm * 64 + gk] : g_Hagg[(size_t)gm * 128 + (gk - 64)];
            }
            As[k][m] = make_float2(v, v);
        }
#pragma unroll
        for (int it = 0; it < 4; it++) {
            int t = tid + it * 256;
            int k = t >> 5, j4 = t & 31;
            *(float4*)&Bs[k][j4 * 4] = *(const float4*)(g_Wcat + (size_t)(k0 + k) * 128 + j4 * 4);
        }
        __syncthreads();
#pragma unroll
        for (int k = 0; k < 32; k++) {
            u64t a0 = *(const u64t*)&As[k][r0 + 0];
            u64t a1 = *(const u64t*)&As[k][r0 + 1];
            u64t a2 = *(const u64t*)&As[k][r0 + 2];
            u64t a3 = *(const u64t*)&As[k][r0 + 3];
            F4U2 B0, B1;
            B0.f = *(float4*)&Bs[k][c0];
            B1.f = *(float4*)&Bs[k][c0 + 4];
#pragma unroll
            for (int p = 0; p < 2; p++) {
                acc2[0][p]     = fma2(a0, B0.u[p], acc2[0][p]);
                acc2[1][p]     = fma2(a1, B0.u[p], acc2[1][p]);
                acc2[2][p]     = fma2(a2, B0.u[p], acc2[2][p]);
                acc2[3][p]     = fma2(a3, B0.u[p], acc2[3][p]);
                acc2[0][2 + p] = fma2(a0, B1.u[p], acc2[0][2 + p]);
                acc2[1][2 + p] = fma2(a1, B1.u[p], acc2[1][2 + p]);
                acc2[2][2 + p] = fma2(a2, B1.u[p], acc2[2][2 + p]);
                acc2[3][2 + p] = fma2(a3, B1.u[p], acc2[3][2 + p]);
            }
        }
        __syncthreads();
    }
    float4 d0v = *(const float4*)(g_dvec + c0);
    float4 d1v = *(const float4*)(g_dvec + c0 + 4);
    float4 u0 = *(const float4*)(bu1 + c0);
    float4 u1 = *(const float4*)(bu1 + c0 + 4);
    float dvv[8] = {d0v.x, d0v.y, d0v.z, d0v.w, d1v.x, d1v.y, d1v.z, d1v.w};
    float uvv[8] = {u0.x, u0.y, u0.z, u0.w, u1.x, u1.y, u1.z, u1.w};
#pragma unroll
    for (int i = 0; i < 4; i++) {
        int gm = row0 + r0 + i;
        if (gm < N_NODES) {
            float dg = g_deg[gm];
            F4U2 A0, A1;
            A0.u[0] = acc2[i][0]; A0.u[1] = acc2[i][1];
            A1.u[0] = acc2[i][2]; A1.u[1] = acc2[i][3];
            float av[8] = {A0.f.x, A0.f.y, A0.f.z, A0.f.w, A1.f.x, A1.f.y, A1.f.z, A1.f.w};
            float o[8];
#pragma unroll
            for (int j = 0; j < 8; j++)
                o[j] = fmaxf(av[j] + fmaf(dg, dvv[j], uvv[j]), 0.f);
            float* op = g_G + (size_t)gm * 128 + c0;
            *(float4*)op = make_float4(o[0], o[1], o[2], o[3]);
            *(float4*)(op + 4) = make_float4(o[4], o[5], o[6], o[7]);
        }
    }
}

// ---------------- GEMM3: out = G @ U2 + bu2   (K=128, N=64) -----------------------
__global__ __launch_bounds__(256) void gemm_upd2_kernel(const float* __restrict__ U2,
                                                        const float* __restrict__ bu2,
                                                        float* __restrict__ out) {
    __shared__ float2 As[32][65];
    __shared__ float  Bs[32][64];
    int row0 = blockIdx.x * 64;
    int tid = threadIdx.x;
    int r0 = (tid >> 4) * 4;
    int c0 = (tid & 15) * 4;
    u64t acc2[4][2];
#pragma unroll
    for (int i = 0; i < 4; i++) {
        acc2[i][0] = 0ull;
        acc2[i][1] = 0ull;
    }

    for (int k0 = 0; k0 < 128; k0 += 32) {
#pragma unroll
        for (int it = 0; it < 8; it++) {
            int t = tid + it * 256;
            int k = t & 31, m = t >> 5;
            int gm = row0 + m;
            float v = (gm < N_NODES) ? g_G[(size_t)gm * 128 + k0 + k] : 0.f;
            As[k][m] = make_float2(v, v);
        }
#pragma unroll
        for (int it = 0; it < 2; it++) {
            int t = tid + it * 256;
            int k = t >> 4, j4 = t & 15;
            *(float4*)&Bs[k][j4 * 4] = *(const float4*)(U2 + (size_t)(k0 + k) * 64 + j4 * 4);
        }
        __syncthreads();
#pragma unroll
        for (int k = 0; k < 32; k++) {
            u64t a0 = *(const u64t*)&As[k][r0 + 0];
            u64t a1 = *(const u64t*)&As[k][r0 + 1];
            u64t a2 = *(const u64t*)&As[k][r0 + 2];
            u64t a3 = *(const u64t*)&As[k][r0 + 3];
            F4U2 B0;
            B0.f = *(float4*)&Bs[k][c0];
#pragma unroll
            for (int p = 0; p < 2; p++) {
                acc2[0][p] = fma2(a0, B0.u[p], acc2[0][p]);
                acc2[1][p] = fma2(a1, B0.u[p], acc2[1][p]);
                acc2[2][p] = fma2(a2, B0.u[p], acc2[2][p]);
                acc2[3][p] = fma2(a3, B0.u[p], acc2[3][p]);
            }
        }
        __syncthreads();
    }
    float4 bv = *(const float4*)(bu2 + c0);
#pragma unroll
    for (int i = 0; i < 4; i++) {
        int gm = row0 + r0 + i;
        if (gm < N_NODES) {
            F4U2 O;
            O.u[0] = acc2[i][0];
            O.u[1] = acc2[i][1];
            *(float4*)(out + (size_t)gm * 64 + c0) =
                make_float4(O.f.x + bv.x, O.f.y + bv.y, O.f.z + bv.z, O.f.w + bv.w);
        }
    }
}

// ---------------- launch ----------------------------------------------------------
extern "C" void kernel_launch(void* const* d_in, const int* in_sizes, int n_in,
                              void* d_out, int out_size) {
    const float* x   = (const float*)d_in[0];
    const int*   ei  = (const int*)d_in[1];
    const float* ef  = (const float*)d_in[2];
    const float* W1  = (const float*)d_in[3];
    const float* b1  = (const float*)d_in[4];
    const float* W2  = (const float*)d_in[5];
    const float* b2  = (const float*)d_in[6];
    const float* U1  = (const float*)d_in[7];
    const float* bu1 = (const float*)d_in[8];
    const float* U2  = (const float*)d_in[9];
    const float* bu2 = (const float*)d_in[10];
    float* out = (float*)d_out;

    prep_kernel<<<193, 128>>>(W2, b2, U1);
    zero_kernel<<<1184, 256>>>();
    gemm_ab_kernel<<<dim3(1563, 2), 256>>>(x, W1);
    edge_kernel<<<N_EDGES / 16, 256>>>(ei, ef, W1, b1);
    gemm_upd1_kernel<<<1563, 256>>>(x, bu1);
    gemm_upd2_kernel<<<1563, 256>>>(U2, bu2, out);
}

// round 3
// speedup vs baseline: 2.1983x; 2.1983x over previous
#include <cuda_runtime.h>
#include <cuda_bf16.h>
#include <math.h>
#include <stdint.h>

#define N_NODES 100000
#define N_EDGES 800000

typedef unsigned int u32;
typedef unsigned long long u64t;

// ---------------- scratch (static __device__ — no allocations allowed) ----------
__device__ float g_AB[(size_t)N_NODES * 256];    // [n][0:128]=x@W1a, [n][128:256]=x@W1b
__device__ float g_Hagg[(size_t)N_NODES * 128];  // sum over in-edges of relu(h)
__device__ float g_G[(size_t)N_NODES * 128];     // relu(update hidden)
__device__ float g_deg[N_NODES];                 // in-degree (float)
__device__ float g_Wcat[192 * 128];              // [U1a (64x128) ; V = W2@U1b (128x128)]
__device__ float g_dvec[128];                    // b2 @ U1b

// pre-packed mma B fragments (hi/lo bf16 pairs), layout: ((s*N + c)*4 + q)*2 + h
__device__ u32 g_Bp1hi[2 * 4096];   // GEMM1: two 64x128 matrices (W1a, W1b)
__device__ u32 g_Bp1lo[2 * 4096];
__device__ u32 g_Bp2hi[12288];      // GEMM2: 192x128 (Wcat)
__device__ u32 g_Bp2lo[12288];
__device__ u32 g_Bp3hi[4096];       // GEMM3: 128x64 (U2)
__device__ u32 g_Bp3lo[4096];

// ---------------- helpers ----------------------------------------------------------
__device__ __forceinline__ u32 bf16bits(float x) {
    return (u32)__bfloat16_as_ushort(__float2bfloat16_rn(x));
}
__device__ __forceinline__ float bf16val(float x) {
    return __bfloat162float(__float2bfloat16_rn(x));
}
__device__ __forceinline__ u32 pack_hi(float x, float y) {
    return bf16bits(x) | (bf16bits(y) << 16);
}
__device__ __forceinline__ u32 pack_lo(float x, float y) {
    return bf16bits(x - bf16val(x)) | (bf16bits(y - bf16val(y)) << 16);
}

__device__ __forceinline__ void mma16816(float c[4], const u32 a[4], u32 b0, u32 b1) {
    asm volatile(
        "mma.sync.aligned.m16n8k16.row.col.f32.bf16.bf16.f32 "
        "{%0,%1,%2,%3}, {%4,%5,%6,%7}, {%8,%9}, {%0,%1,%2,%3};"
        : "+f"(c[0]), "+f"(c[1]), "+f"(c[2]), "+f"(c[3])
        : "r"(a[0]), "r"(a[1]), "r"(a[2]), "r"(a[3]), "r"(b0), "r"(b1));
}

// ---------------- prep: build Wcat and dvec --------------------------------------
__global__ void prep_kernel(const float* __restrict__ W2, const float* __restrict__ b2,
                            const float* __restrict__ U1) {
    int b = blockIdx.x, j = threadIdx.x;  // 128 threads
    if (b < 64) {
        g_Wcat[b * 128 + j] = U1[b * 128 + j];
    } else if (b < 192) {
        int i = b - 64;
        float s = 0.f;
#pragma unroll
        for (int k = 0; k < 64; k++)
            s = fmaf(W2[i * 64 + k], U1[(64 + k) * 128 + j], s);
        g_Wcat[b * 128 + j] = s;
    } else {
        float s = 0.f;
#pragma unroll
        for (int k = 0; k < 64; k++)
            s = fmaf(b2[k], U1[(64 + k) * 128 + j], s);
        g_dvec[j] = s;
    }
}

// ---------------- pack B matrices into mma fragment layout ------------------------
__global__ void pack_b_kernel(int which, const float* __restrict__ W1,
                              const float* __restrict__ U2) {
    u32 *dh, *dl;
    const float* src;
    int K, N;
    if (which == 0)      { dh = g_Bp1hi;        dl = g_Bp1lo;        src = W1;            K = 64;  N = 128; }
    else if (which == 1) { dh = g_Bp1hi + 4096; dl = g_Bp1lo + 4096; src = W1 + 64 * 128; K = 64;  N = 128; }
    else if (which == 2) { dh = g_Bp2hi;        dl = g_Bp2lo;        src = g_Wcat;        K = 192; N = 128; }
    else                 { dh = g_Bp3hi;        dl = g_Bp3lo;        src = U2;            K = 128; N = 64;  }

    int idx = blockIdx.x * blockDim.x + threadIdx.x;
    int total = (K / 16) * N * 8;
    if (idx >= total) return;
    int h = idx & 1;
    int rest = idx >> 1;
    int q = rest & 3;
    int rest2 = rest >> 2;
    int c = rest2 % N;
    int s = rest2 / N;
    int k0 = 16 * s + 2 * q + 8 * h;
    float f0 = src[(size_t)k0 * N + c];
    float f1 = src[(size_t)(k0 + 1) * N + c];
    dh[idx] = pack_hi(f0, f1);
    dl[idx] = pack_lo(f0, f1);
}

// ---------------- zero scratch accumulators ---------------------------------------
__global__ void zero_kernel() {
    size_t idx = (size_t)blockIdx.x * blockDim.x + threadIdx.x;
    size_t stride = (size_t)gridDim.x * blockDim.x;
    size_t tot4 = (size_t)N_NODES * 128 / 4;
    float4 z = make_float4(0.f, 0.f, 0.f, 0.f);
    for (size_t i = idx; i < tot4; i += stride) ((float4*)g_Hagg)[i] = z;
    for (size_t i = idx; i < (size_t)N_NODES; i += stride) g_deg[i] = 0.f;
}

// ---------------- tensor-core GEMM (bf16 2-term split, fp32 accumulate) -----------
// MODE 0: AB[.,cb*128 + n] = x @ W1[cb]          (K=64,  NB=128)
// MODE 1: G = relu([x|Hagg]@Wcat + deg*dvec+bu1) (K=192, NB=128)
// MODE 2: out = G @ U2 + bu2                     (K=128, NB=64)
template <int KTOT, int NB, int MODE>
__global__ __launch_bounds__(256) void mma_gemm_kernel(const float* __restrict__ a_x,
                                                       const float* __restrict__ bias,
                                                       float* __restrict__ outp) {
    constexpr int NJ = NB / 16;        // per-warp n8 tiles (2 warps across N)
    constexpr int NCH = KTOT / 32;     // 32-wide K chunks
    __shared__ __align__(16) u32 sA[2][128][20];  // [hi/lo][row][k-word], pad->20

    const int tid = threadIdx.x;
    const int lane = tid & 31;
    const int warp = tid >> 5;
    const int wm = warp >> 1;          // 0..3
    const int wn = warp & 1;           // 0..1
    const int q = lane & 3;
    const int lr = lane >> 2;          // 0..7
    const int row0 = blockIdx.x * 128;
    const int cb = (MODE == 0) ? blockIdx.y : 0;

    const u32* __restrict__ Bhi;
    const u32* __restrict__ Blo;
    if (MODE == 0)      { Bhi = g_Bp1hi + cb * 4096; Blo = g_Bp1lo + cb * 4096; }
    else if (MODE == 1) { Bhi = g_Bp2hi;             Blo = g_Bp2lo; }
    else                { Bhi = g_Bp3hi;             Blo = g_Bp3lo; }

    float acc[2][NJ][4];
#pragma unroll
    for (int i = 0; i < 2; i++)
#pragma unroll
        for (int j = 0; j < NJ; j++)
#pragma unroll
            for (int p = 0; p < 4; p++) acc[i][j][p] = 0.f;

    for (int ch = 0; ch < NCH; ch++) {
        const int kc0 = ch * 32;
        const float* srcp;
        int ld, koff;
        if (MODE == 0)      { srcp = a_x; ld = 64; koff = kc0; }
        else if (MODE == 1) {
            if (kc0 < 64) { srcp = a_x;              ld = 64;  koff = kc0; }
            else          { srcp = (const float*)g_Hagg; ld = 128; koff = kc0 - 64; }
        } else              { srcp = (const float*)g_G; ld = 128; koff = kc0; }

        __syncthreads();
#pragma unroll
        for (int it = 0; it < 4; it++) {
            int idx = tid + it * 256;
            int m = idx >> 3, fx = idx & 7;
            int gm = row0 + m;
            if (gm >= N_NODES) gm = N_NODES - 1;  // clamp; masked at store
            float4 v = *(const float4*)(srcp + (size_t)gm * ld + koff + fx * 4);
            u32 h0 = pack_hi(v.x, v.y), h1 = pack_hi(v.z, v.w);
            u32 l0 = pack_lo(v.x, v.y), l1 = pack_lo(v.z, v.w);
            *(u64t*)&sA[0][m][fx * 2] = ((u64t)h1 << 32) | h0;
            *(u64t*)&sA[1][m][fx * 2] = ((u64t)l1 << 32) | l0;
        }
        __syncthreads();

#pragma unroll
        for (int s = 0; s < 2; s++) {
            const int sg = ch * 2 + s;
            u32 ah[2][4], al[2][4];
#pragma unroll
            for (int i = 0; i < 2; i++) {
                int rr = wm * 32 + i * 16 + lr;
                ah[i][0] = sA[0][rr][8 * s + q];
                ah[i][1] = sA[0][rr + 8][8 * s + q];
                ah[i][2] = sA[0][rr][8 * s + q + 4];
                ah[i][3] = sA[0][rr + 8][8 * s + q + 4];
                al[i][0] = sA[1][rr][8 * s + q];
                al[i][1] = sA[1][rr + 8][8 * s + q];
                al[i][2] = sA[1][rr][8 * s + q + 4];
                al[i][3] = sA[1][rr + 8][8 * s + q + 4];
            }
#pragma unroll
            for (int j = 0; j < NJ; j++) {
                int c = wn * (NB / 2) + j * 8 + lr;
                int bidx = ((sg * NB + c) * 4 + q) * 2;
                u64t bh = *(const u64t*)(Bhi + bidx);
                u64t bl = *(const u64t*)(Blo + bidx);
                u32 bh0 = (u32)bh, bh1 = (u32)(bh >> 32);
                u32 bl0 = (u32)bl, bl1 = (u32)(bl >> 32);
#pragma unroll
                for (int i = 0; i < 2; i++) {
                    mma16816(acc[i][j], ah[i], bh0, bh1);
                    mma16816(acc[i][j], al[i], bh0, bh1);
                    mma16816(acc[i][j], ah[i], bl0, bl1);
                }
            }
        }
    }

    // ---------------- epilogue ----------------
    const int rbase = row0 + wm * 32 + lr;
#pragma unroll
    for (int i = 0; i < 2; i++) {
        int r0 = rbase + i * 16;
        int r1 = r0 + 8;
#pragma unroll
        for (int j = 0; j < NJ; j++) {
            int n = wn * (NB / 2) + j * 8 + 2 * q;
            float c0 = acc[i][j][0], c1 = acc[i][j][1];
            float c2 = acc[i][j][2], c3 = acc[i][j][3];
            if (MODE == 0) {
                if (r0 < N_NODES)
                    *(float2*)(g_AB + (size_t)r0 * 256 + cb * 128 + n) = make_float2(c0, c1);
                if (r1 < N_NODES)
                    *(float2*)(g_AB + (size_t)r1 * 256 + cb * 128 + n) = make_float2(c2, c3);
            } else if (MODE == 1) {
                float dv0 = g_dvec[n], dv1 = g_dvec[n + 1];
                float bu0 = bias[n], bu1v = bias[n + 1];
                if (r0 < N_NODES) {
                    float dg = g_deg[r0];
                    *(float2*)(g_G + (size_t)r0 * 128 + n) =
                        make_float2(fmaxf(c0 + fmaf(dg, dv0, bu0), 0.f),
                                    fmaxf(c1 + fmaf(dg, dv1, bu1v), 0.f));
                }
                if (r1 < N_NODES) {
                    float dg = g_deg[r1];
                    *(float2*)(g_G + (size_t)r1 * 128 + n) =
                        make_float2(fmaxf(c2 + fmaf(dg, dv0, bu0), 0.f),
                                    fmaxf(c3 + fmaf(dg, dv1, bu1v), 0.f));
                }
            } else {
                float bu0 = bias[n], bu1v = bias[n + 1];
                if (r0 < N_NODES)
                    *(float2*)(outp + (size_t)r0 * 64 + n) = make_float2(c0 + bu0, c1 + bu1v);
                if (r1 < N_NODES)
                    *(float2*)(outp + (size_t)r1 * 64 + n) = make_float2(c2 + bu0, c3 + bu1v);
            }
        }
    }
}

// ---------------- edge kernel (R1 version: 1 edge/warp) ---------------------------
__global__ __launch_bounds__(256) void edge_kernel(const int* __restrict__ ei,
                                                   const float* __restrict__ ef,
                                                   const float* __restrict__ W1,
                                                   const float* __restrict__ b1) {
    __shared__ float s_wc[512];
    __shared__ float s_b1[128];
    for (int t = threadIdx.x; t < 512; t += 256) s_wc[t] = W1[128 * 128 + t];
    if (threadIdx.x < 128) s_b1[threadIdx.x] = b1[threadIdx.x];
    __syncthreads();

    int warp = threadIdx.x >> 5;
    int lane = threadIdx.x & 31;
    int e = blockIdx.x * 8 + warp;
    if (e >= N_EDGES) return;
    int src = ei[e];
    int dst = ei[N_EDGES + e];

    float mv = 0.f;
    if (lane < 4) mv = log1pf(ef[(size_t)e * 4 + lane]);
    float l0 = __shfl_sync(0xffffffffu, mv, 0);
    float l1 = __shfl_sync(0xffffffffu, mv, 1);
    float l2 = __shfl_sync(0xffffffffu, mv, 2);
    float l3 = __shfl_sync(0xffffffffu, mv, 3);

    float4 a = *(const float4*)(g_AB + (size_t)src * 256 + lane * 4);
    float4 b = *(const float4*)(g_AB + (size_t)dst * 256 + 128 + lane * 4);
    float4 w0 = *(const float4*)&s_wc[0 * 128 + lane * 4];
    float4 w1 = *(const float4*)&s_wc[1 * 128 + lane * 4];
    float4 w2 = *(const float4*)&s_wc[2 * 128 + lane * 4];
    float4 w3 = *(const float4*)&s_wc[3 * 128 + lane * 4];
    float4 bb = *(const float4*)&s_b1[lane * 4];

    float4 h;
    h.x = fmaxf(fmaf(l3, w3.x, fmaf(l2, w2.x, fmaf(l1, w1.x, fmaf(l0, w0.x, a.x + b.x + bb.x)))), 0.f);
    h.y = fmaxf(fmaf(l3, w3.y, fmaf(l2, w2.y, fmaf(l1, w1.y, fmaf(l0, w0.y, a.y + b.y + bb.y)))), 0.f);
    h.z = fmaxf(fmaf(l3, w3.z, fmaf(l2, w2.z, fmaf(l1, w1.z, fmaf(l0, w0.z, a.z + b.z + bb.z)))), 0.f);
    h.w = fmaxf(fmaf(l3, w3.w, fmaf(l2, w2.w, fmaf(l1, w1.w, fmaf(l0, w0.w, a.w + b.w + bb.w)))), 0.f);

    atomicAdd((float4*)(g_Hagg + (size_t)dst * 128 + lane * 4), h);
    if (lane == 0) atomicAdd(&g_deg[dst], 1.0f);
}

// ---------------- launch ----------------------------------------------------------
extern "C" void kernel_launch(void* const* d_in, const int* in_sizes, int n_in,
                              void* d_out, int out_size) {
    const float* x   = (const float*)d_in[0];
    const int*   ei  = (const int*)d_in[1];
    const float* ef  = (const float*)d_in[2];
    const float* W1  = (const float*)d_in[3];
    const float* b1  = (const float*)d_in[4];
    const float* W2  = (const float*)d_in[5];
    const float* b2  = (const float*)d_in[6];
    const float* U1  = (const float*)d_in[7];
    const float* bu1 = (const float*)d_in[8];
    const float* U2  = (const float*)d_in[9];
    const float* bu2 = (const float*)d_in[10];
    float* out = (float*)d_out;

    prep_kernel<<<193, 128>>>(W2, b2, U1);
    pack_b_kernel<<<16, 256>>>(0, W1, U2);
    pack_b_kernel<<<16, 256>>>(1, W1, U2);
    pack_b_kernel<<<48, 256>>>(2, W1, U2);
    pack_b_kernel<<<16, 256>>>(3, W1, U2);
    zero_kernel<<<1184, 256>>>();
    mma_gemm_kernel<64, 128, 0><<<dim3(782, 2), 256>>>(x, nullptr, nullptr);
    edge_kernel<<<(N_EDGES + 7) / 8, 256>>>(ei, ef, W1, b1);
    mma_gemm_kernel<192, 128, 1><<<782, 256>>>(x, bu1, nullptr);
    mma_gemm_kernel<128, 64, 2><<<782, 256>>>(x, bu2, out);
}